// round 1
// baseline (speedup 1.0000x reference)
#include <cuda_runtime.h>
#include <math.h>

// ---------------------------------------------------------------------------
// Problem constants (all fixed by the reference)
// ---------------------------------------------------------------------------
#define B_    8
#define M_    1026      // CLS + 1024 tokens + 1 pad row
#define NT_   1024
#define C_    384
#define H_    6
#define D_    64
#define HID_  1536
#define W_    256       // pooling windows (16x16)
#define CAT_  257       // CLS + 256 pooled tokens
#define SCALE_ 0.4082482904638631f   // 6^{-0.5}

// ---------------------------------------------------------------------------
// Scratch (device globals; no allocation allowed)
// ---------------------------------------------------------------------------
__device__ float g_h1  [B_*M_*C_];          // LN1 output, padded (row 1025 = 0)
__device__ float g_qkv [B_*M_*3*C_];        // qkv projections
__device__ float g_att [B_*M_*C_];          // attention output (head concat)
__device__ float g_res [B_*M_*C_];          // h1 + proj(attn)
__device__ float g_h2  [B_*(NT_+1)*C_];     // LN2 output (1025 rows/batch)
__device__ float g_gath[B_*W_*9*C_];        // gathered windows
__device__ float g_tok [B_*W_*C_];          // pooled tokens
__device__ float g_cat [B_*CAT_*C_];        // [cls, tok]
__device__ float g_h3  [B_*CAT_*C_];        // LN3 output
__device__ float g_fc1 [B_*CAT_*HID_];      // gelu(fc1)

// ---------------------------------------------------------------------------
// Helpers
// ---------------------------------------------------------------------------
__device__ __forceinline__ float warpSum(float v) {
#pragma unroll
    for (int o = 16; o > 0; o >>= 1) v += __shfl_xor_sync(0xffffffffu, v, o);
    return v;
}
__device__ __forceinline__ float warpMax(float v) {
#pragma unroll
    for (int o = 16; o > 0; o >>= 1) v = fmaxf(v, __shfl_xor_sync(0xffffffffu, v, o));
    return v;
}

// ---------------------------------------------------------------------------
// LayerNorm: one block per row, 128 threads, C=384 (3 elems/thread)
// ---------------------------------------------------------------------------
__global__ void ln_kernel(const float* __restrict__ in, float* __restrict__ out,
                          const float* __restrict__ gw, const float* __restrict__ gb,
                          int inStride, int outStride) {
    int i = blockIdx.x, b = blockIdx.y;
    const float* xr = in + ((size_t)b * inStride + i) * C_;
    float* yr = out + ((size_t)b * outStride + i) * C_;
    int tid = threadIdx.x;
    float v0 = xr[tid], v1 = xr[tid + 128], v2 = xr[tid + 256];
    __shared__ float sm[4];
    float s = warpSum(v0 + v1 + v2);
    if ((tid & 31) == 0) sm[tid >> 5] = s;
    __syncthreads();
    float mu = (sm[0] + sm[1] + sm[2] + sm[3]) * (1.f / 384.f);
    float d0 = v0 - mu, d1 = v1 - mu, d2 = v2 - mu;
    __syncthreads();
    float q = warpSum(d0 * d0 + d1 * d1 + d2 * d2);
    if ((tid & 31) == 0) sm[tid >> 5] = q;
    __syncthreads();
    float var = (sm[0] + sm[1] + sm[2] + sm[3]) * (1.f / 384.f);
    float rs = rsqrtf(var + 1e-5f);
    yr[tid]       = d0 * rs * gw[tid]       + gb[tid];
    yr[tid + 128] = d1 * rs * gw[tid + 128] + gb[tid + 128];
    yr[tid + 256] = d2 * rs * gw[tid + 256] + gb[tid + 256];
}

__global__ void zero_pad_kernel() {
    g_h1[((size_t)blockIdx.x * M_ + 1025) * C_ + threadIdx.x] = 0.f;
}

// ---------------------------------------------------------------------------
// SGEMM: C[M,N] = A[M,K] * W[N,K]^T (+bias)(+residual)(gelu)
// 128x64x16 tiles, 256 threads, 8x4 per thread
// ---------------------------------------------------------------------------
__global__ void __launch_bounds__(256)
sgemm_kernel(int M, int N, int K,
             const float* __restrict__ A, const float* __restrict__ Wt,
             const float* __restrict__ bias, const float* __restrict__ resid,
             float* __restrict__ Cc, int doGelu) {
    __shared__ __align__(16) float sA[16][128];
    __shared__ __align__(16) float sB[16][64];
    int tid = threadIdx.x;
    int bm = blockIdx.y * 128;
    int bn = blockIdx.x * 64;
    int trow = (tid >> 4) << 3;   // 0..120
    int tcol = (tid & 15) << 2;   // 0..60
    float acc[8][4];
#pragma unroll
    for (int i = 0; i < 8; ++i)
#pragma unroll
        for (int j = 0; j < 4; ++j) acc[i][j] = 0.f;

    int ldRow = tid >> 2;         // 0..63
    int ldK   = (tid & 3) << 2;   // 0,4,8,12

    for (int k0 = 0; k0 < K; k0 += 16) {
#pragma unroll
        for (int i = 0; i < 2; ++i) {
            int r = ldRow + i * 64;
            int gr = bm + r;
            float4 v = make_float4(0.f, 0.f, 0.f, 0.f);
            if (gr < M) v = *(const float4*)(A + (size_t)gr * K + k0 + ldK);
            sA[ldK + 0][r] = v.x; sA[ldK + 1][r] = v.y;
            sA[ldK + 2][r] = v.z; sA[ldK + 3][r] = v.w;
        }
        {
            int gn = bn + ldRow;
            float4 v = make_float4(0.f, 0.f, 0.f, 0.f);
            if (gn < N) v = *(const float4*)(Wt + (size_t)gn * K + k0 + ldK);
            sB[ldK + 0][ldRow] = v.x; sB[ldK + 1][ldRow] = v.y;
            sB[ldK + 2][ldRow] = v.z; sB[ldK + 3][ldRow] = v.w;
        }
        __syncthreads();
#pragma unroll
        for (int kk = 0; kk < 16; ++kk) {
            float ra[8], rb[4];
            *(float4*)&ra[0] = *(const float4*)&sA[kk][trow];
            *(float4*)&ra[4] = *(const float4*)&sA[kk][trow + 4];
            *(float4*)&rb[0] = *(const float4*)&sB[kk][tcol];
#pragma unroll
            for (int i = 0; i < 8; ++i)
#pragma unroll
                for (int j = 0; j < 4; ++j)
                    acc[i][j] = fmaf(ra[i], rb[j], acc[i][j]);
        }
        __syncthreads();
    }

#pragma unroll
    for (int i = 0; i < 8; ++i) {
        int gm = bm + trow + i;
        if (gm >= M) continue;
#pragma unroll
        for (int j = 0; j < 4; ++j) {
            int gn = bn + tcol + j;
            if (gn >= N) continue;
            float v = acc[i][j];
            if (bias)  v += bias[gn];
            if (resid) v += resid[(size_t)gm * N + gn];
            if (doGelu) v = 0.5f * v * (1.f + erff(v * 0.70710678118654752f));
            Cc[(size_t)gm * N + gn] = v;
        }
    }
}

// ---------------------------------------------------------------------------
// Sparse attention for token queries. Mask is separable: tokens (r,c),(r',c')
// co-attend iff rowOK(r,r') && rowOK(c,c'), where rowOK means an even center
// ci in [0,30] exists with |ci-r|<=1 and |ci-r'|<=1.
// One warp per (b,h,token). Lanes: 0 = CLS key, 1..nr*nc = neighbor tokens.
// Softmax includes mask==0 column 1025 as exp(0-m) in the denominator only
// (its v row is zero).
// ---------------------------------------------------------------------------
__global__ void attn_token_kernel() {
    int gw = (blockIdx.x * blockDim.x + threadIdx.x) >> 5;
    int lane = threadIdx.x & 31;
    int t  = gw & 1023;
    int bh = gw >> 10;           // 0..47
    int h = bh % H_;
    int b = bh / H_;
    int r = t >> 5, c = t & 31;

    int rl[5], cl[5];
    int nr = 0, nc = 0;
#pragma unroll
    for (int dr = -2; dr <= 2; ++dr) {
        int rp = r + dr;
        if (rp < 0 || rp > 31) continue;
        int lo = (r > rp ? r : rp) - 1; if (lo < 0) lo = 0;
        int hi = (r < rp ? r : rp) + 1; if (hi > 30) hi = 30;
        int fe = lo + (lo & 1);
        if (fe <= hi) rl[nr++] = rp;
    }
#pragma unroll
    for (int dc = -2; dc <= 2; ++dc) {
        int cp = c + dc;
        if (cp < 0 || cp > 31) continue;
        int lo = (c > cp ? c : cp) - 1; if (lo < 0) lo = 0;
        int hi = (c < cp ? c : cp) + 1; if (hi > 30) hi = 30;
        int fe = lo + (lo & 1);
        if (fe <= hi) cl[nc++] = cp;
    }
    int cnt = 1 + nr * nc;       // <= 26
    int key = 0;                 // lane 0 -> CLS row
    if (lane >= 1 && lane < cnt) {
        int j = lane - 1;
        key = rl[j / nc] * 32 + cl[j % nc] + 1;
    }
    bool active = lane < cnt;

    const float* qp = g_qkv + ((size_t)b * M_ + (t + 1)) * (3 * C_) + h * D_;
    float s = -INFINITY;
    if (active) {
        const float* kp = g_qkv + ((size_t)b * M_ + key) * (3 * C_) + C_ + h * D_;
        float acc = 0.f;
#pragma unroll
        for (int d0 = 0; d0 < D_; d0 += 4) {
            float4 qv = *(const float4*)(qp + d0);
            float4 kv = *(const float4*)(kp + d0);
            acc += qv.x * kv.x + qv.y * kv.y + qv.z * kv.z + qv.w * kv.w;
        }
        s = acc * SCALE_;
    }
    float m = fmaxf(warpMax(s), 0.f);
    float p = active ? expf(s - m) : 0.f;
    float denom = warpSum(p) + expf(-m);   // mask==0 column contributes e^{0-m}
    float inv = 1.f / denom;

    float o0 = 0.f, o1 = 0.f;
    for (int j = 0; j < cnt; ++j) {
        float pj = __shfl_sync(0xffffffffu, p, j);
        int   kj = __shfl_sync(0xffffffffu, key, j);
        const float* vp = g_qkv + ((size_t)b * M_ + kj) * (3 * C_) + 2 * C_ + h * D_;
        o0 += pj * vp[lane];
        o1 += pj * vp[lane + 32];
    }
    float* op = g_att + ((size_t)b * M_ + (t + 1)) * C_ + h * D_;
    op[lane]      = o0 * inv;
    op[lane + 32] = o1 * inv;
}

// CLS query: attends to all 1025 real rows; col 1025 is mask==0.
__global__ void attn_cls_kernel() {
    int b = blockIdx.x / H_;
    int h = blockIdx.x % H_;
    int tid = threadIdx.x;   // 128
    __shared__ float sc[1025];
    __shared__ float sq[64];
    __shared__ float sred[4];
    __shared__ float oacc[128];

    const float* qp = g_qkv + (size_t)(b * M_) * (3 * C_) + h * D_;
    if (tid < 64) sq[tid] = qp[tid];
    __syncthreads();

    for (int j = tid; j < 1025; j += 128) {
        const float* kp = g_qkv + ((size_t)b * M_ + j) * (3 * C_) + C_ + h * D_;
        float acc = 0.f;
#pragma unroll
        for (int d0 = 0; d0 < D_; d0 += 4) {
            float4 kv = *(const float4*)(kp + d0);
            acc += sq[d0] * kv.x + sq[d0 + 1] * kv.y + sq[d0 + 2] * kv.z + sq[d0 + 3] * kv.w;
        }
        sc[j] = acc * SCALE_;
    }
    __syncthreads();

    float m = -INFINITY;
    for (int j = tid; j < 1025; j += 128) m = fmaxf(m, sc[j]);
    m = warpMax(m);
    if ((tid & 31) == 0) sred[tid >> 5] = m;
    __syncthreads();
    m = fmaxf(fmaxf(sred[0], sred[1]), fmaxf(sred[2], sred[3]));
    m = fmaxf(m, 0.f);
    __syncthreads();

    float ls = 0.f;
    for (int j = tid; j < 1025; j += 128) {
        float p = expf(sc[j] - m);
        sc[j] = p;
        ls += p;
    }
    ls = warpSum(ls);
    if ((tid & 31) == 0) sred[tid >> 5] = ls;
    __syncthreads();
    float denom = sred[0] + sred[1] + sred[2] + sred[3] + expf(-m);
    float inv = 1.f / denom;

    int d = tid & 63, half = tid >> 6;
    float acc = 0.f;
    for (int j = half; j < 1025; j += 2)
        acc += sc[j] * g_qkv[((size_t)b * M_ + j) * (3 * C_) + 2 * C_ + h * D_ + d];
    oacc[tid] = acc;
    __syncthreads();
    if (tid < 64)
        g_att[(size_t)(b * M_) * C_ + h * D_ + tid] = (oacc[tid] + oacc[tid + 64]) * inv;
}

// Pad query (row 1025): mask row all zero -> uniform softmax over 1026 cols.
__global__ void attn_pad_kernel() {
    int b = blockIdx.x;
    int ch = threadIdx.x;   // 384 = h*64+d maps to qkv column 768+ch
    const float* base = g_qkv + (size_t)b * M_ * (3 * C_) + 2 * C_ + ch;
    float acc = 0.f;
    for (int mrow = 0; mrow < 1025; ++mrow) acc += base[(size_t)mrow * (3 * C_)];
    g_att[((size_t)b * M_ + 1025) * C_ + ch] = acc * (1.0f / 1026.0f);
}

// ---------------------------------------------------------------------------
// Window gather: gathered[b,w,kk*384+c] = h2[b, hrow(w,kk), c]
// hrow = 1024 for out-of-bounds (replicates reference's -1 -> index 1024)
// ---------------------------------------------------------------------------
__global__ void gather_kernel() {
    int blk = blockIdx.x;                 // b*2304 + w*9 + kk
    int kk = blk % 9;
    int w  = (blk / 9) & 255;
    int b  = blk / (9 * 256);
    int wi = w >> 4, wj = w & 15;
    int rr  = 2 * wi + kk / 3 - 1;
    int cc2 = 2 * wj + kk % 3 - 1;
    int hrow = (rr < 0 || cc2 < 0) ? 1024 : rr * 32 + cc2 + 1;
    const float* src = g_h2 + ((size_t)b * 1025 + hrow) * C_;
    float* dst = g_gath + (((size_t)(b * 256 + w)) * 9 + kk) * C_;
    for (int c = threadIdx.x; c < C_; c += blockDim.x) dst[c] = src[c];
}

__global__ void concat_kernel() {
    int row = blockIdx.x;                 // b*257 + i
    int b = row / CAT_, i = row % CAT_;
    const float* src = (i == 0) ? (g_h2 + (size_t)b * 1025 * C_)
                                : (g_tok + ((size_t)b * W_ + (i - 1)) * C_);
    float* dst = g_cat + (size_t)row * C_;
    for (int c = threadIdx.x; c < C_; c += blockDim.x) dst[c] = src[c];
}

// ---------------------------------------------------------------------------
// Launch
// ---------------------------------------------------------------------------
extern "C" void kernel_launch(void* const* d_in, const int* in_sizes, int n_in,
                              void* d_out, int out_size) {
    const float* x      = (const float*)d_in[0];
    const float* n1w    = (const float*)d_in[1];
    const float* n1b    = (const float*)d_in[2];
    const float* qkv_w  = (const float*)d_in[3];
    const float* proj_w = (const float*)d_in[4];
    const float* proj_b = (const float*)d_in[5];
    const float* n2w    = (const float*)d_in[6];
    const float* n2b    = (const float*)d_in[7];
    const float* pool_w = (const float*)d_in[8];
    const float* pool_b = (const float*)d_in[9];
    const float* n3w    = (const float*)d_in[10];
    const float* n3b    = (const float*)d_in[11];
    const float* fc1_w  = (const float*)d_in[12];
    const float* fc1_b  = (const float*)d_in[13];
    const float* fc2_w  = (const float*)d_in[14];
    const float* fc2_b  = (const float*)d_in[15];
    float* out = (float*)d_out;

    float *h1, *qkvp, *att, *res, *h2, *gath, *tok, *cat, *h3, *fc1o;
    cudaGetSymbolAddress((void**)&h1,   g_h1);
    cudaGetSymbolAddress((void**)&qkvp, g_qkv);
    cudaGetSymbolAddress((void**)&att,  g_att);
    cudaGetSymbolAddress((void**)&res,  g_res);
    cudaGetSymbolAddress((void**)&h2,   g_h2);
    cudaGetSymbolAddress((void**)&gath, g_gath);
    cudaGetSymbolAddress((void**)&tok,  g_tok);
    cudaGetSymbolAddress((void**)&cat,  g_cat);
    cudaGetSymbolAddress((void**)&h3,   g_h3);
    cudaGetSymbolAddress((void**)&fc1o, g_fc1);

    const int MROWS = B_ * M_;        // 8208
    const int PROWS = B_ * W_;        // 2048
    const int CROWS = B_ * CAT_;      // 2056

    // LN1 (+ zero pad row)
    ln_kernel<<<dim3(1025, B_), 128>>>(x, h1, n1w, n1b, 1025, M_);
    zero_pad_kernel<<<B_, C_>>>();

    // QKV
    sgemm_kernel<<<dim3(1152 / 64, (MROWS + 127) / 128), 256>>>(
        MROWS, 3 * C_, C_, h1, qkv_w, nullptr, nullptr, qkvp, 0);

    // Attention (sparse token path + CLS + pad row)
    attn_token_kernel<<<(B_ * H_ * NT_) / 8, 256>>>();
    attn_cls_kernel<<<B_ * H_, 128>>>();
    attn_pad_kernel<<<B_, C_>>>();

    // proj + residual
    sgemm_kernel<<<dim3(C_ / 64, (MROWS + 127) / 128), 256>>>(
        MROWS, C_, C_, att, proj_w, proj_b, h1, res, 0);

    // LN2 (rows 0..1024 per batch)
    ln_kernel<<<dim3(1025, B_), 128>>>(res, h2, n2w, n2b, M_, 1025);

    // gather + pool GEMM
    gather_kernel<<<B_ * W_ * 9, 128>>>();
    sgemm_kernel<<<dim3(C_ / 64, PROWS / 128), 256>>>(
        PROWS, C_, 9 * C_, gath, pool_w, pool_b, nullptr, tok, 0);

    // concat + LN3
    concat_kernel<<<B_ * CAT_, 128>>>();
    ln_kernel<<<dim3(CAT_, B_), 128>>>(cat, h3, n3w, n3b, CAT_, CAT_);

    // MLP
    sgemm_kernel<<<dim3(HID_ / 64, (CROWS + 127) / 128), 256>>>(
        CROWS, HID_, C_, h3, fc1_w, fc1_b, nullptr, fc1o, 1);
    sgemm_kernel<<<dim3(C_ / 64, (CROWS + 127) / 128), 256>>>(
        CROWS, C_, HID_, fc1o, fc2_w, fc2_b, nullptr, out, 0);
}

// round 2
// speedup vs baseline: 1.2498x; 1.2498x over previous
#include <cuda_runtime.h>
#include <math.h>

// ---------------------------------------------------------------------------
// Problem constants
// ---------------------------------------------------------------------------
#define B_    8
#define M_    1026
#define NT_   1024
#define C_    384
#define H_    6
#define D_    64
#define HID_  1536
#define W_    256
#define CAT_  257
#define SCALE_ 0.4082482904638631f

// ---------------------------------------------------------------------------
// Scratch
// ---------------------------------------------------------------------------
__device__ float g_h1  [B_*M_*C_];
__device__ float g_qkv [B_*M_*3*C_];
__device__ float g_att [B_*M_*C_];
__device__ float g_res [B_*M_*C_];
__device__ float g_h2  [B_*(NT_+1)*C_];
__device__ float g_gath[B_*W_*9*C_];
__device__ float g_tok [B_*W_*C_];
__device__ float g_cat [B_*CAT_*C_];
__device__ float g_h3  [B_*CAT_*C_];
__device__ float g_fc1 [B_*CAT_*HID_];

// ---------------------------------------------------------------------------
// Helpers
// ---------------------------------------------------------------------------
__device__ __forceinline__ float warpSum(float v) {
#pragma unroll
    for (int o = 16; o > 0; o >>= 1) v += __shfl_xor_sync(0xffffffffu, v, o);
    return v;
}
__device__ __forceinline__ float warpMax(float v) {
#pragma unroll
    for (int o = 16; o > 0; o >>= 1) v = fmaxf(v, __shfl_xor_sync(0xffffffffu, v, o));
    return v;
}
__device__ __forceinline__ unsigned f2tf(float f) {
    unsigned u;
    asm("cvt.rna.tf32.f32 %0, %1;" : "=r"(u) : "f"(f));
    return u;
}

// ---------------------------------------------------------------------------
// LayerNorm
// ---------------------------------------------------------------------------
__global__ void ln_kernel(const float* __restrict__ in, float* __restrict__ out,
                          const float* __restrict__ gw, const float* __restrict__ gb,
                          int inStride, int outStride) {
    int i = blockIdx.x, b = blockIdx.y;
    const float* xr = in + ((size_t)b * inStride + i) * C_;
    float* yr = out + ((size_t)b * outStride + i) * C_;
    int tid = threadIdx.x;
    float v0 = xr[tid], v1 = xr[tid + 128], v2 = xr[tid + 256];
    __shared__ float sm[4];
    float s = warpSum(v0 + v1 + v2);
    if ((tid & 31) == 0) sm[tid >> 5] = s;
    __syncthreads();
    float mu = (sm[0] + sm[1] + sm[2] + sm[3]) * (1.f / 384.f);
    float d0 = v0 - mu, d1 = v1 - mu, d2 = v2 - mu;
    __syncthreads();
    float q = warpSum(d0 * d0 + d1 * d1 + d2 * d2);
    if ((tid & 31) == 0) sm[tid >> 5] = q;
    __syncthreads();
    float var = (sm[0] + sm[1] + sm[2] + sm[3]) * (1.f / 384.f);
    float rs = rsqrtf(var + 1e-5f);
    yr[tid]       = d0 * rs * gw[tid]       + gb[tid];
    yr[tid + 128] = d1 * rs * gw[tid + 128] + gb[tid + 128];
    yr[tid + 256] = d2 * rs * gw[tid + 256] + gb[tid + 256];
}

__global__ void zero_pad_kernel() {
    g_h1[((size_t)blockIdx.x * M_ + 1025) * C_ + threadIdx.x] = 0.f;
}

// ---------------------------------------------------------------------------
// TF32 tensor-core GEMM: C[M,N] = A[M,K] * W[N,K]^T (+bias)(+resid)(gelu)
// 128x64x32 block tile, 8 warps (4m x 2n), warp tile 32x32 via m16n8k8.
// Requires K % 32 == 0, N % 64 == 0 (true for all call sites).
// ---------------------------------------------------------------------------
#define KP_ 36   // padded K-tile stride (words): frag banks = 4*row + k, conflict-free

__global__ void __launch_bounds__(256)
tgemm_kernel(int M, int N, int K,
             const float* __restrict__ A, const float* __restrict__ Wt,
             const float* __restrict__ bias, const float* __restrict__ resid,
             float* __restrict__ Cc, int doGelu) {
    __shared__ __align__(16) unsigned sA[128][KP_];
    __shared__ __align__(16) unsigned sB[64][KP_];

    int tid  = threadIdx.x;
    int lane = tid & 31;
    int wid  = tid >> 5;
    int wm   = wid & 3;        // 0..3 -> m offset 32*wm
    int wn   = wid >> 2;       // 0..1 -> n offset 32*wn
    int lr   = lane >> 2;      // 0..7
    int lc   = lane & 3;       // 0..3

    int bm = blockIdx.y * 128;
    int bn = blockIdx.x * 64;

    float acc[2][4][4];
#pragma unroll
    for (int mt = 0; mt < 2; ++mt)
#pragma unroll
        for (int nt = 0; nt < 4; ++nt)
#pragma unroll
            for (int e = 0; e < 4; ++e) acc[mt][nt][e] = 0.f;

    int ldRow = tid >> 3;      // 0..31
    int ldC4  = tid & 7;       // float4 index along K (0..7)

    for (int k0 = 0; k0 < K; k0 += 32) {
        // ---- A tile: 128 rows x 32 k ----
#pragma unroll
        for (int i = 0; i < 4; ++i) {
            int r  = ldRow + i * 32;
            int gr = bm + r;
            float4 v = make_float4(0.f, 0.f, 0.f, 0.f);
            if (gr < M) v = *(const float4*)(A + (size_t)gr * K + k0 + ldC4 * 4);
            uint4 t = make_uint4(f2tf(v.x), f2tf(v.y), f2tf(v.z), f2tf(v.w));
            *(uint4*)&sA[r][ldC4 * 4] = t;
        }
        // ---- B tile: 64 n-rows x 32 k ----
#pragma unroll
        for (int i = 0; i < 2; ++i) {
            int n  = ldRow + i * 32;
            int gn = bn + n;
            float4 v = make_float4(0.f, 0.f, 0.f, 0.f);
            if (gn < N) v = *(const float4*)(Wt + (size_t)gn * K + k0 + ldC4 * 4);
            uint4 t = make_uint4(f2tf(v.x), f2tf(v.y), f2tf(v.z), f2tf(v.w));
            *(uint4*)&sB[n][ldC4 * 4] = t;
        }
        __syncthreads();

#pragma unroll
        for (int ks = 0; ks < 4; ++ks) {
            int kk = ks * 8;
            unsigned a[2][4], bf[4][2];
#pragma unroll
            for (int mt = 0; mt < 2; ++mt) {
                int row = wm * 32 + mt * 16 + lr;
                a[mt][0] = sA[row    ][kk + lc];
                a[mt][1] = sA[row + 8][kk + lc];
                a[mt][2] = sA[row    ][kk + lc + 4];
                a[mt][3] = sA[row + 8][kk + lc + 4];
            }
#pragma unroll
            for (int nt = 0; nt < 4; ++nt) {
                int n = wn * 32 + nt * 8 + lr;
                bf[nt][0] = sB[n][kk + lc];
                bf[nt][1] = sB[n][kk + lc + 4];
            }
#pragma unroll
            for (int mt = 0; mt < 2; ++mt)
#pragma unroll
                for (int nt = 0; nt < 4; ++nt) {
                    asm volatile(
                        "mma.sync.aligned.m16n8k8.row.col.f32.tf32.tf32.f32 "
                        "{%0,%1,%2,%3}, {%4,%5,%6,%7}, {%8,%9}, {%0,%1,%2,%3};\n"
                        : "+f"(acc[mt][nt][0]), "+f"(acc[mt][nt][1]),
                          "+f"(acc[mt][nt][2]), "+f"(acc[mt][nt][3])
                        : "r"(a[mt][0]), "r"(a[mt][1]), "r"(a[mt][2]), "r"(a[mt][3]),
                          "r"(bf[nt][0]), "r"(bf[nt][1]));
                }
        }
        __syncthreads();
    }

    // ---- epilogue ----
#pragma unroll
    for (int mt = 0; mt < 2; ++mt) {
#pragma unroll
        for (int nt = 0; nt < 4; ++nt) {
            int col = bn + wn * 32 + nt * 8 + 2 * lc;
            float bx = 0.f, by = 0.f;
            if (bias) { bx = bias[col]; by = bias[col + 1]; }
#pragma unroll
            for (int half = 0; half < 2; ++half) {
                int row = bm + wm * 32 + mt * 16 + lr + half * 8;
                if (row >= M) continue;
                float vx = acc[mt][nt][2 * half + 0] + bx;
                float vy = acc[mt][nt][2 * half + 1] + by;
                if (resid) {
                    const float2 rv = *(const float2*)(resid + (size_t)row * N + col);
                    vx += rv.x; vy += rv.y;
                }
                if (doGelu) {
                    vx = 0.5f * vx * (1.f + erff(vx * 0.70710678118654752f));
                    vy = 0.5f * vy * (1.f + erff(vy * 0.70710678118654752f));
                }
                *(float2*)(Cc + (size_t)row * N + col) = make_float2(vx, vy);
            }
        }
    }
}

// ---------------------------------------------------------------------------
// Sparse attention (token queries): one warp per (b,h,t)
// ---------------------------------------------------------------------------
__global__ void attn_token_kernel() {
    int gw = (blockIdx.x * blockDim.x + threadIdx.x) >> 5;
    int lane = threadIdx.x & 31;
    int t  = gw & 1023;
    int bh = gw >> 10;
    int h = bh % H_;
    int b = bh / H_;
    int r = t >> 5, c = t & 31;

    int rl[5], cl[5];
    int nr = 0, nc = 0;
#pragma unroll
    for (int dr = -2; dr <= 2; ++dr) {
        int rp = r + dr;
        if (rp < 0 || rp > 31) continue;
        int lo = (r > rp ? r : rp) - 1; if (lo < 0) lo = 0;
        int hi = (r < rp ? r : rp) + 1; if (hi > 30) hi = 30;
        int fe = lo + (lo & 1);
        if (fe <= hi) rl[nr++] = rp;
    }
#pragma unroll
    for (int dc = -2; dc <= 2; ++dc) {
        int cp = c + dc;
        if (cp < 0 || cp > 31) continue;
        int lo = (c > cp ? c : cp) - 1; if (lo < 0) lo = 0;
        int hi = (c < cp ? c : cp) + 1; if (hi > 30) hi = 30;
        int fe = lo + (lo & 1);
        if (fe <= hi) cl[nc++] = cp;
    }
    int cnt = 1 + nr * nc;
    int key = 0;
    if (lane >= 1 && lane < cnt) {
        int j = lane - 1;
        key = rl[j / nc] * 32 + cl[j % nc] + 1;
    }
    bool active = lane < cnt;

    const float* qp = g_qkv + ((size_t)b * M_ + (t + 1)) * (3 * C_) + h * D_;
    float s = -INFINITY;
    if (active) {
        const float* kp = g_qkv + ((size_t)b * M_ + key) * (3 * C_) + C_ + h * D_;
        float acc = 0.f;
#pragma unroll
        for (int d0 = 0; d0 < D_; d0 += 4) {
            float4 qv = *(const float4*)(qp + d0);
            float4 kv = *(const float4*)(kp + d0);
            acc += qv.x * kv.x + qv.y * kv.y + qv.z * kv.z + qv.w * kv.w;
        }
        s = acc * SCALE_;
    }
    float m = fmaxf(warpMax(s), 0.f);
    float p = active ? expf(s - m) : 0.f;
    float denom = warpSum(p) + expf(-m);
    float inv = 1.f / denom;

    float o0 = 0.f, o1 = 0.f;
    for (int j = 0; j < cnt; ++j) {
        float pj = __shfl_sync(0xffffffffu, p, j);
        int   kj = __shfl_sync(0xffffffffu, key, j);
        const float* vp = g_qkv + ((size_t)b * M_ + kj) * (3 * C_) + 2 * C_ + h * D_;
        o0 += pj * vp[lane];
        o1 += pj * vp[lane + 32];
    }
    float* op = g_att + ((size_t)b * M_ + (t + 1)) * C_ + h * D_;
    op[lane]      = o0 * inv;
    op[lane + 32] = o1 * inv;
}

__global__ void attn_cls_kernel() {
    int b = blockIdx.x / H_;
    int h = blockIdx.x % H_;
    int tid = threadIdx.x;
    __shared__ float sc[1025];
    __shared__ float sq[64];
    __shared__ float sred[4];
    __shared__ float oacc[128];

    const float* qp = g_qkv + (size_t)(b * M_) * (3 * C_) + h * D_;
    if (tid < 64) sq[tid] = qp[tid];
    __syncthreads();

    for (int j = tid; j < 1025; j += 128) {
        const float* kp = g_qkv + ((size_t)b * M_ + j) * (3 * C_) + C_ + h * D_;
        float acc = 0.f;
#pragma unroll
        for (int d0 = 0; d0 < D_; d0 += 4) {
            float4 kv = *(const float4*)(kp + d0);
            acc += sq[d0] * kv.x + sq[d0 + 1] * kv.y + sq[d0 + 2] * kv.z + sq[d0 + 3] * kv.w;
        }
        sc[j] = acc * SCALE_;
    }
    __syncthreads();

    float m = -INFINITY;
    for (int j = tid; j < 1025; j += 128) m = fmaxf(m, sc[j]);
    m = warpMax(m);
    if ((tid & 31) == 0) sred[tid >> 5] = m;
    __syncthreads();
    m = fmaxf(fmaxf(sred[0], sred[1]), fmaxf(sred[2], sred[3]));
    m = fmaxf(m, 0.f);
    __syncthreads();

    float ls = 0.f;
    for (int j = tid; j < 1025; j += 128) {
        float p = expf(sc[j] - m);
        sc[j] = p;
        ls += p;
    }
    ls = warpSum(ls);
    if ((tid & 31) == 0) sred[tid >> 5] = ls;
    __syncthreads();
    float denom = sred[0] + sred[1] + sred[2] + sred[3] + expf(-m);
    float inv = 1.f / denom;

    int d = tid & 63, half = tid >> 6;
    float acc = 0.f;
    for (int j = half; j < 1025; j += 2)
        acc += sc[j] * g_qkv[((size_t)b * M_ + j) * (3 * C_) + 2 * C_ + h * D_ + d];
    oacc[tid] = acc;
    __syncthreads();
    if (tid < 64)
        g_att[(size_t)(b * M_) * C_ + h * D_ + tid] = (oacc[tid] + oacc[tid + 64]) * inv;
}

__global__ void attn_pad_kernel() {
    int b = blockIdx.x;
    int ch = threadIdx.x;
    const float* base = g_qkv + (size_t)b * M_ * (3 * C_) + 2 * C_ + ch;
    float acc = 0.f;
    for (int mrow = 0; mrow < 1025; ++mrow) acc += base[(size_t)mrow * (3 * C_)];
    g_att[((size_t)b * M_ + 1025) * C_ + ch] = acc * (1.0f / 1026.0f);
}

// ---------------------------------------------------------------------------
// Gather / concat
// ---------------------------------------------------------------------------
__global__ void gather_kernel() {
    int blk = blockIdx.x;
    int kk = blk % 9;
    int w  = (blk / 9) & 255;
    int b  = blk / (9 * 256);
    int wi = w >> 4, wj = w & 15;
    int rr  = 2 * wi + kk / 3 - 1;
    int cc2 = 2 * wj + kk % 3 - 1;
    int hrow = (rr < 0 || cc2 < 0) ? 1024 : rr * 32 + cc2 + 1;
    const float* src = g_h2 + ((size_t)b * 1025 + hrow) * C_;
    float* dst = g_gath + (((size_t)(b * 256 + w)) * 9 + kk) * C_;
    for (int c = threadIdx.x; c < C_; c += blockDim.x) dst[c] = src[c];
}

__global__ void concat_kernel() {
    int row = blockIdx.x;
    int b = row / CAT_, i = row % CAT_;
    const float* src = (i == 0) ? (g_h2 + (size_t)b * 1025 * C_)
                                : (g_tok + ((size_t)b * W_ + (i - 1)) * C_);
    float* dst = g_cat + (size_t)row * C_;
    for (int c = threadIdx.x; c < C_; c += blockDim.x) dst[c] = src[c];
}

// ---------------------------------------------------------------------------
// Launch
// ---------------------------------------------------------------------------
extern "C" void kernel_launch(void* const* d_in, const int* in_sizes, int n_in,
                              void* d_out, int out_size) {
    const float* x      = (const float*)d_in[0];
    const float* n1w    = (const float*)d_in[1];
    const float* n1b    = (const float*)d_in[2];
    const float* qkv_w  = (const float*)d_in[3];
    const float* proj_w = (const float*)d_in[4];
    const float* proj_b = (const float*)d_in[5];
    const float* n2w    = (const float*)d_in[6];
    const float* n2b    = (const float*)d_in[7];
    const float* pool_w = (const float*)d_in[8];
    const float* pool_b = (const float*)d_in[9];
    const float* n3w    = (const float*)d_in[10];
    const float* n3b    = (const float*)d_in[11];
    const float* fc1_w  = (const float*)d_in[12];
    const float* fc1_b  = (const float*)d_in[13];
    const float* fc2_w  = (const float*)d_in[14];
    const float* fc2_b  = (const float*)d_in[15];
    float* out = (float*)d_out;

    float *h1, *qkvp, *att, *res, *h2, *gath, *tok, *cat, *h3, *fc1o;
    cudaGetSymbolAddress((void**)&h1,   g_h1);
    cudaGetSymbolAddress((void**)&qkvp, g_qkv);
    cudaGetSymbolAddress((void**)&att,  g_att);
    cudaGetSymbolAddress((void**)&res,  g_res);
    cudaGetSymbolAddress((void**)&h2,   g_h2);
    cudaGetSymbolAddress((void**)&gath, g_gath);
    cudaGetSymbolAddress((void**)&tok,  g_tok);
    cudaGetSymbolAddress((void**)&cat,  g_cat);
    cudaGetSymbolAddress((void**)&h3,   g_h3);
    cudaGetSymbolAddress((void**)&fc1o, g_fc1);

    const int MROWS = B_ * M_;        // 8208
    const int PROWS = B_ * W_;        // 2048
    const int CROWS = B_ * CAT_;      // 2056

    ln_kernel<<<dim3(1025, B_), 128>>>(x, h1, n1w, n1b, 1025, M_);
    zero_pad_kernel<<<B_, C_>>>();

    tgemm_kernel<<<dim3(1152 / 64, (MROWS + 127) / 128), 256>>>(
        MROWS, 3 * C_, C_, h1, qkv_w, nullptr, nullptr, qkvp, 0);

    attn_token_kernel<<<(B_ * H_ * NT_) / 8, 256>>>();
    attn_cls_kernel<<<B_ * H_, 128>>>();
    attn_pad_kernel<<<B_, C_>>>();

    tgemm_kernel<<<dim3(C_ / 64, (MROWS + 127) / 128), 256>>>(
        MROWS, C_, C_, att, proj_w, proj_b, h1, res, 0);

    ln_kernel<<<dim3(1025, B_), 128>>>(res, h2, n2w, n2b, M_, 1025);

    gather_kernel<<<B_ * W_ * 9, 128>>>();
    tgemm_kernel<<<dim3(C_ / 64, PROWS / 128), 256>>>(
        PROWS, C_, 9 * C_, gath, pool_w, pool_b, nullptr, tok, 0);

    concat_kernel<<<B_ * CAT_, 128>>>();
    ln_kernel<<<dim3(CAT_, B_), 128>>>(cat, h3, n3w, n3b, CAT_, CAT_);

    tgemm_kernel<<<dim3(HID_ / 64, (CROWS + 127) / 128), 256>>>(
        CROWS, HID_, C_, h3, fc1_w, fc1_b, nullptr, fc1o, 1);
    tgemm_kernel<<<dim3(C_ / 64, (CROWS + 127) / 128), 256>>>(
        CROWS, C_, HID_, fc1o, fc2_w, fc2_b, nullptr, out, 0);
}

// round 3
// speedup vs baseline: 2.6879x; 2.1506x over previous
#include <cuda_runtime.h>
#include <math.h>

// ---------------------------------------------------------------------------
// Problem constants
// ---------------------------------------------------------------------------
#define B_    8
#define M_    1026
#define NT_   1024
#define C_    384
#define H_    6
#define D_    64
#define HID_  1536
#define W_    256
#define CAT_  257
#define SCALE_ 0.4082482904638631f

// ---------------------------------------------------------------------------
// Scratch
// ---------------------------------------------------------------------------
__device__ float g_h1  [B_*M_*C_];
__device__ float g_qkv [B_*M_*3*C_];
__device__ float g_att [B_*M_*C_];
__device__ float g_res [B_*M_*C_];
__device__ float g_h2  [B_*(NT_+1)*C_];
__device__ float g_tok [B_*W_*C_];
__device__ float g_cat [B_*CAT_*C_];
__device__ float g_h3  [B_*CAT_*C_];
__device__ float g_fc1 [B_*CAT_*HID_];

// ---------------------------------------------------------------------------
// Helpers
// ---------------------------------------------------------------------------
__device__ __forceinline__ float warpSum(float v) {
#pragma unroll
    for (int o = 16; o > 0; o >>= 1) v += __shfl_xor_sync(0xffffffffu, v, o);
    return v;
}
__device__ __forceinline__ float warpMax(float v) {
#pragma unroll
    for (int o = 16; o > 0; o >>= 1) v = fmaxf(v, __shfl_xor_sync(0xffffffffu, v, o));
    return v;
}
__device__ __forceinline__ unsigned f2tf(float f) {
    unsigned u;
    asm("cvt.rna.tf32.f32 %0, %1;" : "=r"(u) : "f"(f));
    return u;
}
__device__ __forceinline__ void cpasync16(void* smem_dst, const void* gsrc, bool pred) {
    unsigned saddr = (unsigned)__cvta_generic_to_shared(smem_dst);
    int sz = pred ? 16 : 0;
    asm volatile("cp.async.ca.shared.global [%0], [%1], 16, %2;\n"
                 :: "r"(saddr), "l"(gsrc), "r"(sz));
}

// ---------------------------------------------------------------------------
// LayerNorm
// ---------------------------------------------------------------------------
__global__ void ln_kernel(const float* __restrict__ in, float* __restrict__ out,
                          const float* __restrict__ gw, const float* __restrict__ gb,
                          int inStride, int outStride) {
    int i = blockIdx.x, b = blockIdx.y;
    const float* xr = in + ((size_t)b * inStride + i) * C_;
    float* yr = out + ((size_t)b * outStride + i) * C_;
    int tid = threadIdx.x;
    float v0 = xr[tid], v1 = xr[tid + 128], v2 = xr[tid + 256];
    __shared__ float sm[4];
    float s = warpSum(v0 + v1 + v2);
    if ((tid & 31) == 0) sm[tid >> 5] = s;
    __syncthreads();
    float mu = (sm[0] + sm[1] + sm[2] + sm[3]) * (1.f / 384.f);
    float d0 = v0 - mu, d1 = v1 - mu, d2 = v2 - mu;
    __syncthreads();
    float q = warpSum(d0 * d0 + d1 * d1 + d2 * d2);
    if ((tid & 31) == 0) sm[tid >> 5] = q;
    __syncthreads();
    float var = (sm[0] + sm[1] + sm[2] + sm[3]) * (1.f / 384.f);
    float rs = rsqrtf(var + 1e-5f);
    yr[tid]       = d0 * rs * gw[tid]       + gb[tid];
    yr[tid + 128] = d1 * rs * gw[tid + 128] + gb[tid + 128];
    yr[tid + 256] = d2 * rs * gw[tid + 256] + gb[tid + 256];
}

__global__ void zero_pad_kernel() {
    g_h1[((size_t)blockIdx.x * M_ + 1025) * C_ + threadIdx.x] = 0.f;
}

// ---------------------------------------------------------------------------
// TF32 tensor-core GEMM, 2-stage cp.async pipeline.
// C[M,N] = A[M,K]*W[N,K]^T (+bias)(+resid)(gelu).
// gatherMode: A row (b*256+w), col (kk*384+c) -> g_h2[b, hrow(w,kk), c].
// ---------------------------------------------------------------------------
#define KP_ 36
#define TG_SMEM ((2*128*KP_ + 2*64*KP_) * 4)   // 55296 bytes

__global__ void __launch_bounds__(256)
tgemm_kernel(int M, int N, int K,
             const float* __restrict__ A, const float* __restrict__ Wt,
             const float* __restrict__ bias, const float* __restrict__ resid,
             float* __restrict__ Cc, int doGelu, int gatherMode) {
    extern __shared__ float dyn[];
    float (*sA)[128][KP_] = (float(*)[128][KP_])dyn;
    float (*sB)[64][KP_]  = (float(*)[64][KP_])(dyn + 2 * 128 * KP_);

    int tid  = threadIdx.x;
    int lane = tid & 31;
    int wid  = tid >> 5;
    int wm   = wid & 3;
    int wn   = wid >> 2;
    int lr   = lane >> 2;
    int lc   = lane & 3;

    int bm = blockIdx.y * 128;
    int bn = blockIdx.x * 64;

    int ldRow = tid >> 3;   // 0..31
    int ldC4  = tid & 7;    // 0..7

    float acc[2][4][4];
#pragma unroll
    for (int mt = 0; mt < 2; ++mt)
#pragma unroll
        for (int nt = 0; nt < 4; ++nt)
#pragma unroll
            for (int e = 0; e < 4; ++e) acc[mt][nt][e] = 0.f;

    int nIter = K >> 5;

    auto loadTile = [&](int it, int s) {
        int k0 = it << 5;
        if (!gatherMode) {
#pragma unroll
            for (int i = 0; i < 4; ++i) {
                int r = ldRow + i * 32;
                int gr = bm + r;
                bool p = gr < M;
                const float* src = A + (size_t)(p ? gr : 0) * K + k0 + ldC4 * 4;
                cpasync16(&sA[s][r][ldC4 * 4], src, p);
            }
        } else {
            int kk = k0 / 384;
            int c0 = k0 - kk * 384;
#pragma unroll
            for (int i = 0; i < 4; ++i) {
                int r = ldRow + i * 32;
                int gr = bm + r;                 // always < M (2048) here
                int b = gr >> 8, w = gr & 255;
                int wi = w >> 4, wj = w & 15;
                int rr = 2 * wi + kk / 3 - 1;
                int cc = 2 * wj + kk % 3 - 1;
                int hrow = (rr < 0 || cc < 0) ? 1024 : rr * 32 + cc + 1;
                const float* src = A + ((size_t)b * 1025 + hrow) * 384 + c0 + ldC4 * 4;
                cpasync16(&sA[s][r][ldC4 * 4], src, true);
            }
        }
#pragma unroll
        for (int i = 0; i < 2; ++i) {
            int n = ldRow + i * 32;
            int gn = bn + n;
            bool p = gn < N;
            const float* src = Wt + (size_t)(p ? gn : 0) * K + k0 + ldC4 * 4;
            cpasync16(&sB[s][n][ldC4 * 4], src, p);
        }
    };

    loadTile(0, 0);
    asm volatile("cp.async.commit_group;\n");

    for (int it = 0; it < nIter; ++it) {
        int s = it & 1;
        if (it + 1 < nIter) {
            loadTile(it + 1, s ^ 1);
            asm volatile("cp.async.commit_group;\n");
            asm volatile("cp.async.wait_group 1;\n");
        } else {
            asm volatile("cp.async.wait_group 0;\n");
        }
        __syncthreads();

#pragma unroll
        for (int ks = 0; ks < 4; ++ks) {
            int kk = ks * 8;
            unsigned a[2][4], bf[4][2];
#pragma unroll
            for (int mt = 0; mt < 2; ++mt) {
                int row = wm * 32 + mt * 16 + lr;
                a[mt][0] = f2tf(sA[s][row    ][kk + lc]);
                a[mt][1] = f2tf(sA[s][row + 8][kk + lc]);
                a[mt][2] = f2tf(sA[s][row    ][kk + lc + 4]);
                a[mt][3] = f2tf(sA[s][row + 8][kk + lc + 4]);
            }
#pragma unroll
            for (int nt = 0; nt < 4; ++nt) {
                int n = wn * 32 + nt * 8 + lr;
                bf[nt][0] = f2tf(sB[s][n][kk + lc]);
                bf[nt][1] = f2tf(sB[s][n][kk + lc + 4]);
            }
#pragma unroll
            for (int mt = 0; mt < 2; ++mt)
#pragma unroll
                for (int nt = 0; nt < 4; ++nt) {
                    asm volatile(
                        "mma.sync.aligned.m16n8k8.row.col.f32.tf32.tf32.f32 "
                        "{%0,%1,%2,%3}, {%4,%5,%6,%7}, {%8,%9}, {%0,%1,%2,%3};\n"
                        : "+f"(acc[mt][nt][0]), "+f"(acc[mt][nt][1]),
                          "+f"(acc[mt][nt][2]), "+f"(acc[mt][nt][3])
                        : "r"(a[mt][0]), "r"(a[mt][1]), "r"(a[mt][2]), "r"(a[mt][3]),
                          "r"(bf[nt][0]), "r"(bf[nt][1]));
                }
        }
        __syncthreads();
    }

    // ---- epilogue ----
#pragma unroll
    for (int mt = 0; mt < 2; ++mt) {
#pragma unroll
        for (int nt = 0; nt < 4; ++nt) {
            int col = bn + wn * 32 + nt * 8 + 2 * lc;
            float bx = 0.f, by = 0.f;
            if (bias) { bx = bias[col]; by = bias[col + 1]; }
#pragma unroll
            for (int half = 0; half < 2; ++half) {
                int row = bm + wm * 32 + mt * 16 + lr + half * 8;
                if (row >= M) continue;
                float vx = acc[mt][nt][2 * half + 0] + bx;
                float vy = acc[mt][nt][2 * half + 1] + by;
                if (resid) {
                    const float2 rv = *(const float2*)(resid + (size_t)row * N + col);
                    vx += rv.x; vy += rv.y;
                }
                if (doGelu) {
                    vx = 0.5f * vx * (1.f + erff(vx * 0.70710678118654752f));
                    vy = 0.5f * vy * (1.f + erff(vy * 0.70710678118654752f));
                }
                *(float2*)(Cc + (size_t)row * N + col) = make_float2(vx, vy);
            }
        }
    }
}

// ---------------------------------------------------------------------------
// Sparse attention (token queries): one warp per (b,h,t).
// QK pass: coalesced per-key loads + butterfly reduction (2 keys/iter).
// ---------------------------------------------------------------------------
__global__ void attn_token_kernel() {
    int gw = (blockIdx.x * blockDim.x + threadIdx.x) >> 5;
    int lane = threadIdx.x & 31;
    int t  = gw & 1023;
    int bh = gw >> 10;
    int h = bh % H_;
    int b = bh / H_;
    int r = t >> 5, c = t & 31;

    int rl[5], cl[5];
    int nr = 0, nc = 0;
#pragma unroll
    for (int dr = -2; dr <= 2; ++dr) {
        int rp = r + dr;
        if (rp < 0 || rp > 31) continue;
        int lo = (r > rp ? r : rp) - 1; if (lo < 0) lo = 0;
        int hi = (r < rp ? r : rp) + 1; if (hi > 30) hi = 30;
        int fe = lo + (lo & 1);
        if (fe <= hi) rl[nr++] = rp;
    }
#pragma unroll
    for (int dc = -2; dc <= 2; ++dc) {
        int cp = c + dc;
        if (cp < 0 || cp > 31) continue;
        int lo = (c > cp ? c : cp) - 1; if (lo < 0) lo = 0;
        int hi = (c < cp ? c : cp) + 1; if (hi > 30) hi = 30;
        int fe = lo + (lo & 1);
        if (fe <= hi) cl[nc++] = cp;
    }
    int cnt = 1 + nr * nc;       // <= 26
    int key = 0;                 // lane 0 -> CLS
    if (lane >= 1 && lane < cnt) {
        int j = lane - 1;
        key = rl[j / nc] * 32 + cl[j % nc] + 1;
    }

    const float* qp = g_qkv + ((size_t)b * M_ + (t + 1)) * (3 * C_) + h * D_;
    float q0 = qp[lane], q1 = qp[lane + 32];
    const float* kbase = g_qkv + (size_t)b * M_ * (3 * C_) + C_ + h * D_;

    // --- pass 1: scores, coalesced ---
    float s = -INFINITY;
    for (int j0 = 0; j0 < 26; j0 += 2) {
        if (j0 >= cnt) break;
        int ka = __shfl_sync(0xffffffffu, key, j0);
        int kb = __shfl_sync(0xffffffffu, key, j0 + 1);
        const float* pa = kbase + (size_t)ka * (3 * C_);
        const float* pb = kbase + (size_t)kb * (3 * C_);
        float da = q0 * pa[lane] + q1 * pa[lane + 32];
        float db = q0 * pb[lane] + q1 * pb[lane + 32];
#pragma unroll
        for (int o = 16; o > 0; o >>= 1) {
            da += __shfl_xor_sync(0xffffffffu, da, o);
            db += __shfl_xor_sync(0xffffffffu, db, o);
        }
        if (lane == j0)     s = da * SCALE_;
        if (lane == j0 + 1) s = db * SCALE_;
    }
    if (lane >= cnt) s = -INFINITY;

    float m = fmaxf(warpMax(s), 0.f);
    float p = (lane < cnt) ? expf(s - m) : 0.f;
    float denom = warpSum(p) + expf(-m);
    float inv = 1.f / denom;

    // --- pass 2: PV, coalesced ---
    const float* vbase = g_qkv + (size_t)b * M_ * (3 * C_) + 2 * C_ + h * D_;
    float o0 = 0.f, o1 = 0.f;
    for (int j = 0; j < cnt; ++j) {
        float pj = __shfl_sync(0xffffffffu, p, j);
        int   kj = __shfl_sync(0xffffffffu, key, j);
        const float* vp = vbase + (size_t)kj * (3 * C_);
        o0 += pj * vp[lane];
        o1 += pj * vp[lane + 32];
    }
    float* op = g_att + ((size_t)b * M_ + (t + 1)) * C_ + h * D_;
    op[lane]      = o0 * inv;
    op[lane + 32] = o1 * inv;
}

// CLS query: 256 threads, 8 warps.
__global__ void attn_cls_kernel() {
    int b = blockIdx.x / H_;
    int h = blockIdx.x % H_;
    int tid = threadIdx.x;   // 256
    __shared__ float sc[1025];
    __shared__ float sq[64];
    __shared__ float sred[8];
    __shared__ float oacc[256];

    const float* qp = g_qkv + (size_t)(b * M_) * (3 * C_) + h * D_;
    if (tid < 64) sq[tid] = qp[tid];
    __syncthreads();

    for (int j = tid; j < 1025; j += 256) {
        const float* kp = g_qkv + ((size_t)b * M_ + j) * (3 * C_) + C_ + h * D_;
        float acc = 0.f;
#pragma unroll
        for (int d0 = 0; d0 < D_; d0 += 4) {
            float4 kv = *(const float4*)(kp + d0);
            acc += sq[d0] * kv.x + sq[d0 + 1] * kv.y + sq[d0 + 2] * kv.z + sq[d0 + 3] * kv.w;
        }
        sc[j] = acc * SCALE_;
    }
    __syncthreads();

    float m = -INFINITY;
    for (int j = tid; j < 1025; j += 256) m = fmaxf(m, sc[j]);
    m = warpMax(m);
    if ((tid & 31) == 0) sred[tid >> 5] = m;
    __syncthreads();
    m = 0.f;
#pragma unroll
    for (int wr = 0; wr < 8; ++wr) m = fmaxf(m, sred[wr]);
    __syncthreads();

    float ls = 0.f;
    for (int j = tid; j < 1025; j += 256) {
        float pv = expf(sc[j] - m);
        sc[j] = pv;
        ls += pv;
    }
    ls = warpSum(ls);
    if ((tid & 31) == 0) sred[tid >> 5] = ls;
    __syncthreads();
    float denom = expf(-m);
#pragma unroll
    for (int wr = 0; wr < 8; ++wr) denom += sred[wr];
    float inv = 1.f / denom;

    int d = tid & 63, grp = tid >> 6;   // 4 row groups
    float acc = 0.f;
    for (int j = grp; j < 1025; j += 4)
        acc += sc[j] * g_qkv[((size_t)b * M_ + j) * (3 * C_) + 2 * C_ + h * D_ + d];
    oacc[tid] = acc;
    __syncthreads();
    if (tid < 64)
        g_att[(size_t)(b * M_) * C_ + h * D_ + tid] =
            (oacc[tid] + oacc[tid + 64] + oacc[tid + 128] + oacc[tid + 192]) * inv;
}

// Pad query: parallel over rows. grid (12, B), block 256 = 32ch x 8 rowgroups.
__global__ void attn_pad_kernel() {
    int b = blockIdx.y;
    int cg = blockIdx.x;
    int tid = threadIdx.x;
    int cl = tid & 31;
    int rg = tid >> 5;
    int ch = cg * 32 + cl;
    const float* base = g_qkv + (size_t)b * M_ * (3 * C_) + 2 * C_ + ch;
    float acc = 0.f;
    for (int mrow = rg; mrow < 1025; mrow += 8)
        acc += base[(size_t)mrow * (3 * C_)];
    __shared__ float sm2[8][32];
    sm2[rg][cl] = acc;
    __syncthreads();
    if (tid < 32) {
        float a = 0.f;
#pragma unroll
        for (int rr = 0; rr < 8; ++rr) a += sm2[rr][tid];
        g_att[((size_t)b * M_ + 1025) * C_ + cg * 32 + tid] = a * (1.0f / 1026.0f);
    }
}

__global__ void concat_kernel() {
    int row = blockIdx.x;
    int b = row / CAT_, i = row % CAT_;
    const float* src = (i == 0) ? (g_h2 + (size_t)b * 1025 * C_)
                                : (g_tok + ((size_t)b * W_ + (i - 1)) * C_);
    float* dst = g_cat + (size_t)row * C_;
    for (int c = threadIdx.x; c < C_; c += blockDim.x) dst[c] = src[c];
}

// ---------------------------------------------------------------------------
// Launch
// ---------------------------------------------------------------------------
extern "C" void kernel_launch(void* const* d_in, const int* in_sizes, int n_in,
                              void* d_out, int out_size) {
    const float* x      = (const float*)d_in[0];
    const float* n1w    = (const float*)d_in[1];
    const float* n1b    = (const float*)d_in[2];
    const float* qkv_w  = (const float*)d_in[3];
    const float* proj_w = (const float*)d_in[4];
    const float* proj_b = (const float*)d_in[5];
    const float* n2w    = (const float*)d_in[6];
    const float* n2b    = (const float*)d_in[7];
    const float* pool_w = (const float*)d_in[8];
    const float* pool_b = (const float*)d_in[9];
    const float* n3w    = (const float*)d_in[10];
    const float* n3b    = (const float*)d_in[11];
    const float* fc1_w  = (const float*)d_in[12];
    const float* fc1_b  = (const float*)d_in[13];
    const float* fc2_w  = (const float*)d_in[14];
    const float* fc2_b  = (const float*)d_in[15];
    float* out = (float*)d_out;

    float *h1, *qkvp, *att, *res, *h2, *tok, *cat, *h3, *fc1o;
    cudaGetSymbolAddress((void**)&h1,   g_h1);
    cudaGetSymbolAddress((void**)&qkvp, g_qkv);
    cudaGetSymbolAddress((void**)&att,  g_att);
    cudaGetSymbolAddress((void**)&res,  g_res);
    cudaGetSymbolAddress((void**)&h2,   g_h2);
    cudaGetSymbolAddress((void**)&tok,  g_tok);
    cudaGetSymbolAddress((void**)&cat,  g_cat);
    cudaGetSymbolAddress((void**)&h3,   g_h3);
    cudaGetSymbolAddress((void**)&fc1o, g_fc1);

    static int smemSet = 0;
    if (!smemSet) {
        cudaFuncSetAttribute(tgemm_kernel,
                             cudaFuncAttributeMaxDynamicSharedMemorySize, TG_SMEM);
        smemSet = 1;
    }

    const int MROWS = B_ * M_;        // 8208
    const int PROWS = B_ * W_;        // 2048
    const int CROWS = B_ * CAT_;      // 2056

    ln_kernel<<<dim3(1025, B_), 128>>>(x, h1, n1w, n1b, 1025, M_);
    zero_pad_kernel<<<B_, C_>>>();

    tgemm_kernel<<<dim3(1152 / 64, (MROWS + 127) / 128), 256, TG_SMEM>>>(
        MROWS, 3 * C_, C_, h1, qkv_w, nullptr, nullptr, qkvp, 0, 0);

    attn_token_kernel<<<(B_ * H_ * NT_) / 8, 256>>>();
    attn_cls_kernel<<<B_ * H_, 256>>>();
    attn_pad_kernel<<<dim3(12, B_), 256>>>();

    tgemm_kernel<<<dim3(C_ / 64, (MROWS + 127) / 128), 256, TG_SMEM>>>(
        MROWS, C_, C_, att, proj_w, proj_b, h1, res, 0, 0);

    ln_kernel<<<dim3(1025, B_), 128>>>(res, h2, n2w, n2b, M_, 1025);

    // pool GEMM with fused window gather (A = g_h2)
    tgemm_kernel<<<dim3(C_ / 64, PROWS / 128), 256, TG_SMEM>>>(
        PROWS, C_, 9 * C_, h2, pool_w, pool_b, nullptr, tok, 0, 1);

    concat_kernel<<<B_ * CAT_, 128>>>();
    ln_kernel<<<dim3(CAT_, B_), 128>>>(cat, h3, n3w, n3b, CAT_, CAT_);

    tgemm_kernel<<<dim3(HID_ / 64, (CROWS + 127) / 128), 256, TG_SMEM>>>(
        CROWS, HID_, C_, h3, fc1_w, fc1_b, nullptr, fc1o, 1, 0);
    tgemm_kernel<<<dim3(C_ / 64, (CROWS + 127) / 128), 256, TG_SMEM>>>(
        CROWS, C_, HID_, fc1o, fc2_w, fc2_b, nullptr, out, 0, 0);
}